// round 5
// baseline (speedup 1.0000x reference)
#include <cuda_runtime.h>
#include <cstdint>

#define NN 50000      // nodes
#define NE 1250000    // edges
#define DN 64         // node feat
#define DE 16         // edge feat
#define DH 64         // hidden

// ---------------------------------------------------------------------------
// Scratch (device globals; no allocation allowed)
// ---------------------------------------------------------------------------
__device__ float g_srcpart[NN * DH];   // node_features @ W_m1[0:64]
__device__ float g_hsum[NN * DH];      // segment-sum of relu hidden
__device__ int   g_deg[NN];            // in-degree per node
__device__ float g_Wc[DH * DH];        // W_m2 @ W_u1[64:128]
__device__ float g_bc[DH];             // b_m2 @ W_u1[64:128]

// ---------------------------------------------------------------------------
// pre_kernel: one launch does
//   blocks [0, GB)            : g_srcpart = node_f @ w_m1[0:64]   (64-row tiles)
//   blocks [GB, GB+ZB)        : zero g_hsum + g_deg
//   block  GB+ZB              : fold Wc = w_m2 @ w_u1[64:128], bc = b_m2 @ ...
// ---------------------------------------------------------------------------
#define GB 782    // ceil(50000/64)
#define ZB 3125   // NN*DH/4 / 256
__global__ void __launch_bounds__(256, 5)
pre_kernel(const float* __restrict__ A,      // node features
           const float* __restrict__ w_m1,
           const float* __restrict__ w_m2,
           const float* __restrict__ b_m2,
           const float* __restrict__ w_u1) {
    __shared__ float As[64 * 66];
    const int tid = threadIdx.x;

    if (blockIdx.x < GB) {
        const int row0 = blockIdx.x * 64;
        // stage 64x64 A tile
        for (int idx = tid; idx < 64 * 64; idx += 256) {
            int r = idx >> 6, k = idx & 63;
            int row = row0 + r;
            As[r * 66 + k] = (row < NN) ? A[(size_t)row * 64 + k] : 0.f;
        }
        __syncthreads();

        const int tc = tid & 15, tr = tid >> 4;
        const int j0 = tc * 4, r0 = tr * 4;
        float4 acc[4];
        #pragma unroll
        for (int i = 0; i < 4; i++) acc[i] = make_float4(0.f, 0.f, 0.f, 0.f);

        #pragma unroll 8
        for (int k = 0; k < 64; k++) {
            float4 w = *reinterpret_cast<const float4*>(&w_m1[k * 64 + j0]);
            #pragma unroll
            for (int i = 0; i < 4; i++) {
                float a = As[(r0 + i) * 66 + k];
                acc[i].x += a * w.x; acc[i].y += a * w.y;
                acc[i].z += a * w.z; acc[i].w += a * w.w;
            }
        }
        #pragma unroll
        for (int i = 0; i < 4; i++) {
            int row = row0 + r0 + i;
            if (row < NN)
                *reinterpret_cast<float4*>(&g_srcpart[(size_t)row * 64 + j0]) = acc[i];
        }
    } else if (blockIdx.x < GB + ZB) {
        int idx = (blockIdx.x - GB) * 256 + tid;
        reinterpret_cast<float4*>(g_hsum)[idx] = make_float4(0.f, 0.f, 0.f, 0.f);
        if (idx < NN) g_deg[idx] = 0;
    } else {
        for (int idx = tid; idx < DH * DH; idx += 256) {
            int k = idx >> 6, j = idx & 63;
            float s = 0.f;
            #pragma unroll 8
            for (int m = 0; m < DH; m++)
                s += w_m2[k * DH + m] * w_u1[(DN + m) * DH + j];
            g_Wc[idx] = s;
        }
        if (tid < DH) {
            float s = 0.f;
            #pragma unroll 8
            for (int m = 0; m < DH; m++)
                s += b_m2[m] * w_u1[(DN + m) * DH + tid];
            g_bc[tid] = s;
        }
    }
}

// ---------------------------------------------------------------------------
// Edge kernel v3: 32 edges / 256-thread block, 2 edges x 4 cols per thread.
// Small reg tile -> 5 blocks/SM (~62% occ) to hide L2 gather + REDG latency.
// ---------------------------------------------------------------------------
__global__ void __launch_bounds__(256, 5)
edge_kernel(const float* __restrict__ ef,
            const int* __restrict__ eidx,
            const float* __restrict__ w_m1,
            const float* __restrict__ b_m1) {
    __shared__ float Es[32 * 17];
    __shared__ int s_sh[32];
    __shared__ int d_sh[32];
    const int e0 = blockIdx.x * 32;
    const int tid = threadIdx.x;

    if (tid < 32) {
        int e = e0 + tid;
        int s = 0, d = 0;
        if (e < NE) {
            s = eidx[e];
            d = eidx[NE + e];
            atomicAdd(&g_deg[d], 1);
        }
        s_sh[tid] = s;
        d_sh[tid] = d;
    }
    if (tid < 128) {      // 32 edges x 4 float4 = 128 loads
        int r = tid >> 2, q = tid & 3;
        int e = e0 + r;
        float4 v = make_float4(0.f, 0.f, 0.f, 0.f);
        if (e < NE)
            v = reinterpret_cast<const float4*>(ef)[(size_t)e * 4 + q];
        Es[r * 17 + q * 4 + 0] = v.x;
        Es[r * 17 + q * 4 + 1] = v.y;
        Es[r * 17 + q * 4 + 2] = v.z;
        Es[r * 17 + q * 4 + 3] = v.w;
    }
    __syncthreads();

    const int tc = tid & 15, tr = tid >> 4;
    const int j0 = tc * 4, r0 = tr * 2;

    // Prefetch both srcpart gathers (independent L2 hits).
    float4 sp[2];
    #pragma unroll
    for (int i = 0; i < 2; i++) {
        int e = e0 + r0 + i;
        const float* p = &g_srcpart[(size_t)s_sh[r0 + i] * 64 + j0];
        sp[i] = (e < NE) ? *reinterpret_cast<const float4*>(p)
                         : make_float4(0.f, 0.f, 0.f, 0.f);
    }

    float4 acc[2];
    #pragma unroll
    for (int i = 0; i < 2; i++) acc[i] = make_float4(0.f, 0.f, 0.f, 0.f);

    #pragma unroll
    for (int k = 0; k < 16; k++) {
        float4 w = *reinterpret_cast<const float4*>(&w_m1[(DN + k) * 64 + j0]);
        #pragma unroll
        for (int i = 0; i < 2; i++) {
            float a = Es[(r0 + i) * 17 + k];
            acc[i].x += a * w.x; acc[i].y += a * w.y;
            acc[i].z += a * w.z; acc[i].w += a * w.w;
        }
    }

    float4 b = *reinterpret_cast<const float4*>(&b_m1[j0]);

    #pragma unroll
    for (int i = 0; i < 2; i++) {
        int e = e0 + r0 + i;
        if (e < NE) {
            float hx = fmaxf(acc[i].x + sp[i].x + b.x, 0.f);
            float hy = fmaxf(acc[i].y + sp[i].y + b.y, 0.f);
            float hz = fmaxf(acc[i].z + sp[i].z + b.z, 0.f);
            float hw = fmaxf(acc[i].w + sp[i].w + b.w, 0.f);
            float* p = &g_hsum[(size_t)d_sh[r0 + i] * 64 + j0];
            asm volatile("red.global.add.v4.f32 [%0], {%1, %2, %3, %4};"
                         :: "l"(p), "f"(hx), "f"(hy), "f"(hz), "f"(hw)
                         : "memory");
        }
    }
}

// ---------------------------------------------------------------------------
// Fused node update v2: 64-row tiles, 4 rows x 4 cols per thread.
// T = relu(X@Wu1a + Hsum@Wc + deg*bc + b_u1) staged in smem,
// then out = T @ w_u2 + b_u2.
// ---------------------------------------------------------------------------
__global__ void __launch_bounds__(256, 5)
fused_node_kernel(const float* __restrict__ X,
                  const float* __restrict__ w_u1,
                  const float* __restrict__ b_u1,
                  const float* __restrict__ w_u2,
                  const float* __restrict__ b_u2,
                  float* __restrict__ out) {
    __shared__ float As[64 * 66];
    const int row0 = blockIdx.x * 64;
    const int tid = threadIdx.x;
    const int tc = tid & 15, tr = tid >> 4;
    const int j0 = tc * 4, r0 = tr * 4;

    float4 acc[4];
    #pragma unroll
    for (int i = 0; i < 4; i++) acc[i] = make_float4(0.f, 0.f, 0.f, 0.f);

    // pass 1: X @ w_u1[0:64]
    for (int idx = tid; idx < 64 * 64; idx += 256) {
        int r = idx >> 6, k = idx & 63;
        int row = row0 + r;
        As[r * 66 + k] = (row < NN) ? X[(size_t)row * 64 + k] : 0.f;
    }
    __syncthreads();
    #pragma unroll 8
    for (int k = 0; k < 64; k++) {
        float4 w = *reinterpret_cast<const float4*>(&w_u1[k * 64 + j0]);
        #pragma unroll
        for (int i = 0; i < 4; i++) {
            float a = As[(r0 + i) * 66 + k];
            acc[i].x += a * w.x; acc[i].y += a * w.y;
            acc[i].z += a * w.z; acc[i].w += a * w.w;
        }
    }
    __syncthreads();

    // pass 2: Hsum @ Wc
    for (int idx = tid; idx < 64 * 64; idx += 256) {
        int r = idx >> 6, k = idx & 63;
        int row = row0 + r;
        As[r * 66 + k] = (row < NN) ? g_hsum[(size_t)row * 64 + k] : 0.f;
    }
    __syncthreads();
    #pragma unroll 8
    for (int k = 0; k < 64; k++) {
        float4 w = *reinterpret_cast<const float4*>(&g_Wc[k * 64 + j0]);
        #pragma unroll
        for (int i = 0; i < 4; i++) {
            float a = As[(r0 + i) * 66 + k];
            acc[i].x += a * w.x; acc[i].y += a * w.y;
            acc[i].z += a * w.z; acc[i].w += a * w.w;
        }
    }
    __syncthreads();

    // T = relu(acc + deg*bc + b_u1) -> stage into As
    {
        float4 bc = *reinterpret_cast<const float4*>(&g_bc[j0]);
        float4 bu = *reinterpret_cast<const float4*>(&b_u1[j0]);
        #pragma unroll
        for (int i = 0; i < 4; i++) {
            int r = r0 + i;
            int row = row0 + r;
            float dg = (row < NN) ? (float)g_deg[row] : 0.f;
            As[r * 66 + j0 + 0] = fmaxf(acc[i].x + dg * bc.x + bu.x, 0.f);
            As[r * 66 + j0 + 1] = fmaxf(acc[i].y + dg * bc.y + bu.y, 0.f);
            As[r * 66 + j0 + 2] = fmaxf(acc[i].z + dg * bc.z + bu.z, 0.f);
            As[r * 66 + j0 + 3] = fmaxf(acc[i].w + dg * bc.w + bu.w, 0.f);
        }
    }
    __syncthreads();

    // pass 3: out = T @ w_u2 + b_u2
    #pragma unroll
    for (int i = 0; i < 4; i++) acc[i] = make_float4(0.f, 0.f, 0.f, 0.f);
    #pragma unroll 8
    for (int k = 0; k < 64; k++) {
        float4 w = *reinterpret_cast<const float4*>(&w_u2[k * 64 + j0]);
        #pragma unroll
        for (int i = 0; i < 4; i++) {
            float a = As[(r0 + i) * 66 + k];
            acc[i].x += a * w.x; acc[i].y += a * w.y;
            acc[i].z += a * w.z; acc[i].w += a * w.w;
        }
    }

    float4 b2 = *reinterpret_cast<const float4*>(&b_u2[j0]);
    #pragma unroll
    for (int i = 0; i < 4; i++) {
        int row = row0 + r0 + i;
        if (row < NN) {
            float4 v;
            v.x = acc[i].x + b2.x; v.y = acc[i].y + b2.y;
            v.z = acc[i].z + b2.z; v.w = acc[i].w + b2.w;
            *reinterpret_cast<float4*>(&out[(size_t)row * 64 + j0]) = v;
        }
    }
}

// ---------------------------------------------------------------------------
// Launch
// ---------------------------------------------------------------------------
extern "C" void kernel_launch(void* const* d_in, const int* in_sizes, int n_in,
                              void* d_out, int out_size) {
    const float* node_f = (const float*)d_in[0];
    const float* edge_f = (const float*)d_in[1];
    const int*   eidx   = (const int*)d_in[2];
    const float* w_m1   = (const float*)d_in[3];
    const float* b_m1   = (const float*)d_in[4];
    const float* w_m2   = (const float*)d_in[5];
    const float* b_m2   = (const float*)d_in[6];
    const float* w_u1   = (const float*)d_in[7];
    const float* b_u1   = (const float*)d_in[8];
    const float* w_u2   = (const float*)d_in[9];
    const float* b_u2   = (const float*)d_in[10];
    float* out = (float*)d_out;

    const int nodeBlocks = (NN + 63) / 64;     // 782
    const int edgeBlocks = (NE + 31) / 32;     // 39063

    pre_kernel<<<GB + ZB + 1, 256>>>(node_f, w_m1, w_m2, b_m2, w_u1);
    edge_kernel<<<edgeBlocks, 256>>>(edge_f, eidx, w_m1, b_m1);
    fused_node_kernel<<<nodeBlocks, 256>>>(node_f, w_u1, b_u1, w_u2, b_u2, out);
}

// round 6
// speedup vs baseline: 1.2780x; 1.2780x over previous
#include <cuda_runtime.h>
#include <cstdint>

#define NN 50000      // nodes
#define NE 1250000    // edges
#define DN 64         // node feat
#define DE 16         // edge feat
#define DH 64         // hidden

// ---------------------------------------------------------------------------
// Scratch (device globals; no allocation allowed)
// ---------------------------------------------------------------------------
__device__ float g_srcpart[NN * DH];   // node_features @ W_m1[0:64]
__device__ float g_hsum[NN * DH];      // segment-sum of relu hidden
__device__ int   g_deg[NN];            // in-degree per node
__device__ float g_Wc[DH * DH];        // W_m2 @ W_u1[64:128]
__device__ float g_bc[DH];             // b_m2 @ W_u1[64:128]

// ---------------------------------------------------------------------------
// init: blocks [0,ZB) zero g_hsum/g_deg.
//       blocks ZB+k (k<64): Wc row k, coalesced over tid.
//       block  ZB+64: bc.
// ---------------------------------------------------------------------------
#define ZB 3125   // NN*DH/4 / 256
__global__ void init_kernel(const float* __restrict__ w_m2,
                            const float* __restrict__ b_m2,
                            const float* __restrict__ w_u1) {
    const int tid = threadIdx.x;
    if (blockIdx.x < ZB) {
        int idx = blockIdx.x * 256 + tid;
        reinterpret_cast<float4*>(g_hsum)[idx] = make_float4(0.f, 0.f, 0.f, 0.f);
        if (idx < NN) g_deg[idx] = 0;
    } else if (blockIdx.x < ZB + 64) {
        int k = blockIdx.x - ZB;
        if (tid < DH) {
            float s = 0.f;
            #pragma unroll 8
            for (int m = 0; m < DH; m++)
                s += w_m2[k * DH + m] * w_u1[(DN + m) * DH + tid];   // coalesced over tid
            g_Wc[k * DH + tid] = s;
        }
    } else {
        if (tid < DH) {
            float s = 0.f;
            #pragma unroll 8
            for (int m = 0; m < DH; m++)
                s += b_m2[m] * w_u1[(DN + m) * DH + tid];
            g_bc[tid] = s;
        }
    }
}

// ---------------------------------------------------------------------------
// srcpart = node_features @ w_m1[0:64].  64-row tiles, 4 rows x 4 cols/thread.
// ---------------------------------------------------------------------------
__global__ void __launch_bounds__(256, 5)
srcpart_kernel(const float* __restrict__ A,
               const float* __restrict__ w_m1) {
    __shared__ float As[64 * 66];
    const int row0 = blockIdx.x * 64;
    const int tid = threadIdx.x;

    for (int idx = tid; idx < 64 * 64; idx += 256) {
        int r = idx >> 6, k = idx & 63;
        int row = row0 + r;
        As[r * 66 + k] = (row < NN) ? A[(size_t)row * 64 + k] : 0.f;
    }
    __syncthreads();

    const int tc = tid & 15, tr = tid >> 4;
    const int j0 = tc * 4, r0 = tr * 4;
    float4 acc[4];
    #pragma unroll
    for (int i = 0; i < 4; i++) acc[i] = make_float4(0.f, 0.f, 0.f, 0.f);

    #pragma unroll 8
    for (int k = 0; k < 64; k++) {
        float4 w = *reinterpret_cast<const float4*>(&w_m1[k * 64 + j0]);
        #pragma unroll
        for (int i = 0; i < 4; i++) {
            float a = As[(r0 + i) * 66 + k];
            acc[i].x += a * w.x; acc[i].y += a * w.y;
            acc[i].z += a * w.z; acc[i].w += a * w.w;
        }
    }
    #pragma unroll
    for (int i = 0; i < 4; i++) {
        int row = row0 + r0 + i;
        if (row < NN)
            *reinterpret_cast<float4*>(&g_srcpart[(size_t)row * 64 + j0]) = acc[i];
    }
}

// ---------------------------------------------------------------------------
// Edge kernel (R4 config, best measured): 64 edges / 256-thread block,
// 4 edges x 4 cols per thread, 4 blocks/SM.
// ---------------------------------------------------------------------------
__global__ void __launch_bounds__(256, 4)
edge_kernel(const float* __restrict__ ef,
            const int* __restrict__ eidx,
            const float* __restrict__ w_m1,
            const float* __restrict__ b_m1) {
    __shared__ float Es[64 * 17];
    __shared__ int s_sh[64];
    __shared__ int d_sh[64];
    const int e0 = blockIdx.x * 64;
    const int tid = threadIdx.x;

    if (tid < 64) {
        int e = e0 + tid;
        int s = 0, d = 0;
        if (e < NE) {
            s = eidx[e];
            d = eidx[NE + e];
            atomicAdd(&g_deg[d], 1);
        }
        s_sh[tid] = s;
        d_sh[tid] = d;
    }
    {
        int r = tid >> 2, q = tid & 3;   // 64 edges x 4 float4 = 256 loads
        int e = e0 + r;
        float4 v = make_float4(0.f, 0.f, 0.f, 0.f);
        if (e < NE)
            v = reinterpret_cast<const float4*>(ef)[(size_t)e * 4 + q];
        Es[r * 17 + q * 4 + 0] = v.x;
        Es[r * 17 + q * 4 + 1] = v.y;
        Es[r * 17 + q * 4 + 2] = v.z;
        Es[r * 17 + q * 4 + 3] = v.w;
    }
    __syncthreads();

    const int tc = tid & 15, tr = tid >> 4;
    const int j0 = tc * 4, r0 = tr * 4;

    // Prefetch the 4 srcpart gathers early (independent L2 hits, MLP=4).
    float4 sp[4];
    #pragma unroll
    for (int i = 0; i < 4; i++) {
        int e = e0 + r0 + i;
        const float* p = &g_srcpart[(size_t)s_sh[r0 + i] * 64 + j0];
        sp[i] = (e < NE) ? *reinterpret_cast<const float4*>(p)
                         : make_float4(0.f, 0.f, 0.f, 0.f);
    }

    float4 acc[4];
    #pragma unroll
    for (int i = 0; i < 4; i++) acc[i] = make_float4(0.f, 0.f, 0.f, 0.f);

    #pragma unroll
    for (int k = 0; k < 16; k++) {
        float4 w = *reinterpret_cast<const float4*>(&w_m1[(DN + k) * 64 + j0]);
        #pragma unroll
        for (int i = 0; i < 4; i++) {
            float a = Es[(r0 + i) * 17 + k];
            acc[i].x += a * w.x; acc[i].y += a * w.y;
            acc[i].z += a * w.z; acc[i].w += a * w.w;
        }
    }

    float4 b = *reinterpret_cast<const float4*>(&b_m1[j0]);

    #pragma unroll
    for (int i = 0; i < 4; i++) {
        int e = e0 + r0 + i;
        if (e < NE) {
            float hx = fmaxf(acc[i].x + sp[i].x + b.x, 0.f);
            float hy = fmaxf(acc[i].y + sp[i].y + b.y, 0.f);
            float hz = fmaxf(acc[i].z + sp[i].z + b.z, 0.f);
            float hw = fmaxf(acc[i].w + sp[i].w + b.w, 0.f);
            float* p = &g_hsum[(size_t)d_sh[r0 + i] * 64 + j0];
            asm volatile("red.global.add.v4.f32 [%0], {%1, %2, %3, %4};"
                         :: "l"(p), "f"(hx), "f"(hy), "f"(hz), "f"(hw)
                         : "memory");
        }
    }
}

// ---------------------------------------------------------------------------
// Fused node update: 64-row tiles, 4 rows x 4 cols per thread, 5 blocks/SM.
// T = relu(X@Wu1a + Hsum@Wc + deg*bc + b_u1) staged in smem,
// then out = T @ w_u2 + b_u2.
// ---------------------------------------------------------------------------
__global__ void __launch_bounds__(256, 5)
fused_node_kernel(const float* __restrict__ X,
                  const float* __restrict__ w_u1,
                  const float* __restrict__ b_u1,
                  const float* __restrict__ w_u2,
                  const float* __restrict__ b_u2,
                  float* __restrict__ out) {
    __shared__ float As[64 * 66];
    const int row0 = blockIdx.x * 64;
    const int tid = threadIdx.x;
    const int tc = tid & 15, tr = tid >> 4;
    const int j0 = tc * 4, r0 = tr * 4;

    float4 acc[4];
    #pragma unroll
    for (int i = 0; i < 4; i++) acc[i] = make_float4(0.f, 0.f, 0.f, 0.f);

    // pass 1: X @ w_u1[0:64]
    for (int idx = tid; idx < 64 * 64; idx += 256) {
        int r = idx >> 6, k = idx & 63;
        int row = row0 + r;
        As[r * 66 + k] = (row < NN) ? X[(size_t)row * 64 + k] : 0.f;
    }
    __syncthreads();
    #pragma unroll 8
    for (int k = 0; k < 64; k++) {
        float4 w = *reinterpret_cast<const float4*>(&w_u1[k * 64 + j0]);
        #pragma unroll
        for (int i = 0; i < 4; i++) {
            float a = As[(r0 + i) * 66 + k];
            acc[i].x += a * w.x; acc[i].y += a * w.y;
            acc[i].z += a * w.z; acc[i].w += a * w.w;
        }
    }
    __syncthreads();

    // pass 2: Hsum @ Wc
    for (int idx = tid; idx < 64 * 64; idx += 256) {
        int r = idx >> 6, k = idx & 63;
        int row = row0 + r;
        As[r * 66 + k] = (row < NN) ? g_hsum[(size_t)row * 64 + k] : 0.f;
    }
    __syncthreads();
    #pragma unroll 8
    for (int k = 0; k < 64; k++) {
        float4 w = *reinterpret_cast<const float4*>(&g_Wc[k * 64 + j0]);
        #pragma unroll
        for (int i = 0; i < 4; i++) {
            float a = As[(r0 + i) * 66 + k];
            acc[i].x += a * w.x; acc[i].y += a * w.y;
            acc[i].z += a * w.z; acc[i].w += a * w.w;
        }
    }
    __syncthreads();

    // T = relu(acc + deg*bc + b_u1) -> stage into As
    {
        float4 bc = *reinterpret_cast<const float4*>(&g_bc[j0]);
        float4 bu = *reinterpret_cast<const float4*>(&b_u1[j0]);
        #pragma unroll
        for (int i = 0; i < 4; i++) {
            int r = r0 + i;
            int row = row0 + r;
            float dg = (row < NN) ? (float)g_deg[row] : 0.f;
            As[r * 66 + j0 + 0] = fmaxf(acc[i].x + dg * bc.x + bu.x, 0.f);
            As[r * 66 + j0 + 1] = fmaxf(acc[i].y + dg * bc.y + bu.y, 0.f);
            As[r * 66 + j0 + 2] = fmaxf(acc[i].z + dg * bc.z + bu.z, 0.f);
            As[r * 66 + j0 + 3] = fmaxf(acc[i].w + dg * bc.w + bu.w, 0.f);
        }
    }
    __syncthreads();

    // pass 3: out = T @ w_u2 + b_u2
    #pragma unroll
    for (int i = 0; i < 4; i++) acc[i] = make_float4(0.f, 0.f, 0.f, 0.f);
    #pragma unroll 8
    for (int k = 0; k < 64; k++) {
        float4 w = *reinterpret_cast<const float4*>(&w_u2[k * 64 + j0]);
        #pragma unroll
        for (int i = 0; i < 4; i++) {
            float a = As[(r0 + i) * 66 + k];
            acc[i].x += a * w.x; acc[i].y += a * w.y;
            acc[i].z += a * w.z; acc[i].w += a * w.w;
        }
    }

    float4 b2 = *reinterpret_cast<const float4*>(&b_u2[j0]);
    #pragma unroll
    for (int i = 0; i < 4; i++) {
        int row = row0 + r0 + i;
        if (row < NN) {
            float4 v;
            v.x = acc[i].x + b2.x; v.y = acc[i].y + b2.y;
            v.z = acc[i].z + b2.z; v.w = acc[i].w + b2.w;
            *reinterpret_cast<float4*>(&out[(size_t)row * 64 + j0]) = v;
        }
    }
}

// ---------------------------------------------------------------------------
// Launch
// ---------------------------------------------------------------------------
extern "C" void kernel_launch(void* const* d_in, const int* in_sizes, int n_in,
                              void* d_out, int out_size) {
    const float* node_f = (const float*)d_in[0];
    const float* edge_f = (const float*)d_in[1];
    const int*   eidx   = (const int*)d_in[2];
    const float* w_m1   = (const float*)d_in[3];
    const float* b_m1   = (const float*)d_in[4];
    const float* w_m2   = (const float*)d_in[5];
    const float* b_m2   = (const float*)d_in[6];
    const float* w_u1   = (const float*)d_in[7];
    const float* b_u1   = (const float*)d_in[8];
    const float* w_u2   = (const float*)d_in[9];
    const float* b_u2   = (const float*)d_in[10];
    float* out = (float*)d_out;

    const int nodeBlocks = (NN + 63) / 64;     // 782
    const int edgeBlocks = (NE + 63) / 64;     // 19532

    init_kernel<<<ZB + 65, 256>>>(w_m2, b_m2, w_u1);
    srcpart_kernel<<<nodeBlocks, 256>>>(node_f, w_m1);
    edge_kernel<<<edgeBlocks, 256>>>(edge_f, eidx, w_m1, b_m1);
    fused_node_kernel<<<nodeBlocks, 256>>>(node_f, w_u1, b_u1, w_u2, b_u2, out);
}

// round 7
// speedup vs baseline: 1.5522x; 1.2145x over previous
#include <cuda_runtime.h>
#include <cstdint>

#define NN 50000      // nodes
#define NE 1250000    // edges
#define DN 64         // node feat
#define DE 16         // edge feat
#define DH 64         // hidden

// ---------------------------------------------------------------------------
// Scratch (device globals; no allocation allowed)
// ---------------------------------------------------------------------------
__device__ float g_srcpart[NN * DH];   // node_features @ W_m1[0:64]
__device__ float g_xu[NN * DH];        // node_features @ W_u1[0:64]
__device__ float g_hsum[NN * DH];      // segment-sum of relu hidden
__device__ int   g_deg[NN];            // in-degree per node
__device__ float g_Wc[DH * DH];        // W_m2 @ W_u1[64:128]
__device__ float g_bc[DH];             // b_m2 @ W_u1[64:128]

// ---------------------------------------------------------------------------
// init: blocks [0,ZB) zero g_hsum/g_deg.
//       blocks ZB+k (k<64): Wc row k (coalesced over tid).  block ZB+64: bc.
// ---------------------------------------------------------------------------
#define ZB 3125   // NN*DH/4 / 256
__global__ void init_kernel(const float* __restrict__ w_m2,
                            const float* __restrict__ b_m2,
                            const float* __restrict__ w_u1) {
    const int tid = threadIdx.x;
    if (blockIdx.x < ZB) {
        int idx = blockIdx.x * 256 + tid;
        reinterpret_cast<float4*>(g_hsum)[idx] = make_float4(0.f, 0.f, 0.f, 0.f);
        if (idx < NN) g_deg[idx] = 0;
    } else if (blockIdx.x < ZB + 64) {
        int k = blockIdx.x - ZB;
        if (tid < DH) {
            float s = 0.f;
            #pragma unroll 8
            for (int m = 0; m < DH; m++)
                s += w_m2[k * DH + m] * w_u1[(DN + m) * DH + tid];
            g_Wc[k * DH + tid] = s;
        }
    } else {
        if (tid < DH) {
            float s = 0.f;
            #pragma unroll 8
            for (int m = 0; m < DH; m++)
                s += b_m2[m] * w_u1[(DN + m) * DH + tid];
            g_bc[tid] = s;
        }
    }
}

// ---------------------------------------------------------------------------
// pre_gemm: stage X tile (128x64) once, produce BOTH
//   g_srcpart = X @ w_m1[0:64]   and   g_xu = X @ w_u1[0:64].
// 8 rows x 4 cols per thread.
// ---------------------------------------------------------------------------
__global__ void pre_gemm_kernel(const float* __restrict__ X,
                                const float* __restrict__ w_m1,
                                const float* __restrict__ w_u1) {
    __shared__ float As[128 * 66];
    const int row0 = blockIdx.x * 128;
    const int tid = threadIdx.x;

    for (int idx = tid; idx < 128 * 64; idx += 256) {
        int r = idx >> 6, k = idx & 63;
        int row = row0 + r;
        As[r * 66 + k] = (row < NN) ? X[(size_t)row * 64 + k] : 0.f;
    }
    __syncthreads();

    const int tc = tid & 15, tr = tid >> 4;
    const int j0 = tc * 4, r0 = tr * 8;
    float4 acc[8];

    // --- srcpart ---
    #pragma unroll
    for (int i = 0; i < 8; i++) acc[i] = make_float4(0.f, 0.f, 0.f, 0.f);
    #pragma unroll 8
    for (int k = 0; k < 64; k++) {
        float4 w = *reinterpret_cast<const float4*>(&w_m1[k * 64 + j0]);
        #pragma unroll
        for (int i = 0; i < 8; i++) {
            float a = As[(r0 + i) * 66 + k];
            acc[i].x += a * w.x; acc[i].y += a * w.y;
            acc[i].z += a * w.z; acc[i].w += a * w.w;
        }
    }
    #pragma unroll
    for (int i = 0; i < 8; i++) {
        int row = row0 + r0 + i;
        if (row < NN)
            *reinterpret_cast<float4*>(&g_srcpart[(size_t)row * 64 + j0]) = acc[i];
    }

    // --- xu ---
    #pragma unroll
    for (int i = 0; i < 8; i++) acc[i] = make_float4(0.f, 0.f, 0.f, 0.f);
    #pragma unroll 8
    for (int k = 0; k < 64; k++) {
        float4 w = *reinterpret_cast<const float4*>(&w_u1[k * 64 + j0]);
        #pragma unroll
        for (int i = 0; i < 8; i++) {
            float a = As[(r0 + i) * 66 + k];
            acc[i].x += a * w.x; acc[i].y += a * w.y;
            acc[i].z += a * w.z; acc[i].w += a * w.w;
        }
    }
    #pragma unroll
    for (int i = 0; i < 8; i++) {
        int row = row0 + r0 + i;
        if (row < NN)
            *reinterpret_cast<float4*>(&g_xu[(size_t)row * 64 + j0]) = acc[i];
    }
}

// ---------------------------------------------------------------------------
// Edge kernel (best measured config): 64 edges / 256-thread block,
// 4 edges x 4 cols per thread, 4 blocks/SM.
// ---------------------------------------------------------------------------
__global__ void __launch_bounds__(256, 4)
edge_kernel(const float* __restrict__ ef,
            const int* __restrict__ eidx,
            const float* __restrict__ w_m1,
            const float* __restrict__ b_m1) {
    __shared__ float Es[64 * 17];
    __shared__ int s_sh[64];
    __shared__ int d_sh[64];
    const int e0 = blockIdx.x * 64;
    const int tid = threadIdx.x;

    if (tid < 64) {
        int e = e0 + tid;
        int s = 0, d = 0;
        if (e < NE) {
            s = eidx[e];
            d = eidx[NE + e];
            atomicAdd(&g_deg[d], 1);
        }
        s_sh[tid] = s;
        d_sh[tid] = d;
    }
    {
        int r = tid >> 2, q = tid & 3;   // 64 edges x 4 float4 = 256 loads
        int e = e0 + r;
        float4 v = make_float4(0.f, 0.f, 0.f, 0.f);
        if (e < NE)
            v = reinterpret_cast<const float4*>(ef)[(size_t)e * 4 + q];
        Es[r * 17 + q * 4 + 0] = v.x;
        Es[r * 17 + q * 4 + 1] = v.y;
        Es[r * 17 + q * 4 + 2] = v.z;
        Es[r * 17 + q * 4 + 3] = v.w;
    }
    __syncthreads();

    const int tc = tid & 15, tr = tid >> 4;
    const int j0 = tc * 4, r0 = tr * 4;

    // Prefetch the 4 srcpart gathers early (independent L2 hits, MLP=4).
    float4 sp[4];
    #pragma unroll
    for (int i = 0; i < 4; i++) {
        int e = e0 + r0 + i;
        const float* p = &g_srcpart[(size_t)s_sh[r0 + i] * 64 + j0];
        sp[i] = (e < NE) ? *reinterpret_cast<const float4*>(p)
                         : make_float4(0.f, 0.f, 0.f, 0.f);
    }

    float4 acc[4];
    #pragma unroll
    for (int i = 0; i < 4; i++) acc[i] = make_float4(0.f, 0.f, 0.f, 0.f);

    #pragma unroll
    for (int k = 0; k < 16; k++) {
        float4 w = *reinterpret_cast<const float4*>(&w_m1[(DN + k) * 64 + j0]);
        #pragma unroll
        for (int i = 0; i < 4; i++) {
            float a = Es[(r0 + i) * 17 + k];
            acc[i].x += a * w.x; acc[i].y += a * w.y;
            acc[i].z += a * w.z; acc[i].w += a * w.w;
        }
    }

    float4 b = *reinterpret_cast<const float4*>(&b_m1[j0]);

    #pragma unroll
    for (int i = 0; i < 4; i++) {
        int e = e0 + r0 + i;
        if (e < NE) {
            float hx = fmaxf(acc[i].x + sp[i].x + b.x, 0.f);
            float hy = fmaxf(acc[i].y + sp[i].y + b.y, 0.f);
            float hz = fmaxf(acc[i].z + sp[i].z + b.z, 0.f);
            float hw = fmaxf(acc[i].w + sp[i].w + b.w, 0.f);
            float* p = &g_hsum[(size_t)d_sh[r0 + i] * 64 + j0];
            asm volatile("red.global.add.v4.f32 [%0], {%1, %2, %3, %4};"
                         :: "l"(p), "f"(hx), "f"(hy), "f"(hz), "f"(hw)
                         : "memory");
        }
    }
}

// ---------------------------------------------------------------------------
// Fused node update v3: 128-row tiles, 8 rows x 4 cols/thread, TWO passes:
//   T = relu(Hsum@Wc + xu + deg*bc + b_u1)  (xu read directly per-thread)
//   out = T @ w_u2 + b_u2
// ---------------------------------------------------------------------------
__global__ void fused_node_kernel(const float* __restrict__ w_u2,
                                  const float* __restrict__ b_u1,
                                  const float* __restrict__ b_u2,
                                  float* __restrict__ out) {
    __shared__ float As[128 * 66];
    const int row0 = blockIdx.x * 128;
    const int tid = threadIdx.x;
    const int tc = tid & 15, tr = tid >> 4;
    const int j0 = tc * 4, r0 = tr * 8;

    // stage Hsum tile
    for (int idx = tid; idx < 128 * 64; idx += 256) {
        int r = idx >> 6, k = idx & 63;
        int row = row0 + r;
        As[r * 66 + k] = (row < NN) ? g_hsum[(size_t)row * 64 + k] : 0.f;
    }
    __syncthreads();

    float4 acc[8];
    #pragma unroll
    for (int i = 0; i < 8; i++) acc[i] = make_float4(0.f, 0.f, 0.f, 0.f);
    #pragma unroll 8
    for (int k = 0; k < 64; k++) {
        float4 w = *reinterpret_cast<const float4*>(&g_Wc[k * 64 + j0]);
        #pragma unroll
        for (int i = 0; i < 8; i++) {
            float a = As[(r0 + i) * 66 + k];
            acc[i].x += a * w.x; acc[i].y += a * w.y;
            acc[i].z += a * w.z; acc[i].w += a * w.w;
        }
    }
    __syncthreads();

    // T = relu(acc + xu + deg*bc + b_u1) -> stage into As
    {
        float4 bc = *reinterpret_cast<const float4*>(&g_bc[j0]);
        float4 bu = *reinterpret_cast<const float4*>(&b_u1[j0]);
        #pragma unroll
        for (int i = 0; i < 8; i++) {
            int r = r0 + i;
            int row = row0 + r;
            if (row < NN) {
                float4 xu = *reinterpret_cast<const float4*>(
                    &g_xu[(size_t)row * 64 + j0]);
                float dg = (float)g_deg[row];
                As[r * 66 + j0 + 0] = fmaxf(acc[i].x + xu.x + dg * bc.x + bu.x, 0.f);
                As[r * 66 + j0 + 1] = fmaxf(acc[i].y + xu.y + dg * bc.y + bu.y, 0.f);
                As[r * 66 + j0 + 2] = fmaxf(acc[i].z + xu.z + dg * bc.z + bu.z, 0.f);
                As[r * 66 + j0 + 3] = fmaxf(acc[i].w + xu.w + dg * bc.w + bu.w, 0.f);
            } else {
                As[r * 66 + j0 + 0] = 0.f;
                As[r * 66 + j0 + 1] = 0.f;
                As[r * 66 + j0 + 2] = 0.f;
                As[r * 66 + j0 + 3] = 0.f;
            }
        }
    }
    __syncthreads();

    // out = T @ w_u2 + b_u2
    #pragma unroll
    for (int i = 0; i < 8; i++) acc[i] = make_float4(0.f, 0.f, 0.f, 0.f);
    #pragma unroll 8
    for (int k = 0; k < 64; k++) {
        float4 w = *reinterpret_cast<const float4*>(&w_u2[k * 64 + j0]);
        #pragma unroll
        for (int i = 0; i < 8; i++) {
            float a = As[(r0 + i) * 66 + k];
            acc[i].x += a * w.x; acc[i].y += a * w.y;
            acc[i].z += a * w.z; acc[i].w += a * w.w;
        }
    }

    float4 b2 = *reinterpret_cast<const float4*>(&b_u2[j0]);
    #pragma unroll
    for (int i = 0; i < 8; i++) {
        int row = row0 + r0 + i;
        if (row < NN) {
            float4 v;
            v.x = acc[i].x + b2.x; v.y = acc[i].y + b2.y;
            v.z = acc[i].z + b2.z; v.w = acc[i].w + b2.w;
            *reinterpret_cast<float4*>(&out[(size_t)row * 64 + j0]) = v;
        }
    }
}

// ---------------------------------------------------------------------------
// Launch
// ---------------------------------------------------------------------------
extern "C" void kernel_launch(void* const* d_in, const int* in_sizes, int n_in,
                              void* d_out, int out_size) {
    const float* node_f = (const float*)d_in[0];
    const float* edge_f = (const float*)d_in[1];
    const int*   eidx   = (const int*)d_in[2];
    const float* w_m1   = (const float*)d_in[3];
    const float* b_m1   = (const float*)d_in[4];
    const float* w_m2   = (const float*)d_in[5];
    const float* b_m2   = (const float*)d_in[6];
    const float* w_u1   = (const float*)d_in[7];
    const float* b_u1   = (const float*)d_in[8];
    const float* w_u2   = (const float*)d_in[9];
    const float* b_u2   = (const float*)d_in[10];
    float* out = (float*)d_out;

    const int nodeBlocks = (NN + 127) / 128;   // 391
    const int edgeBlocks = (NE + 63) / 64;     // 19532

    init_kernel<<<ZB + 65, 256>>>(w_m2, b_m2, w_u1);
    pre_gemm_kernel<<<nodeBlocks, 256>>>(node_f, w_m1, w_u1);
    edge_kernel<<<edgeBlocks, 256>>>(edge_f, eidx, w_m1, b_m1);
    fused_node_kernel<<<nodeBlocks, 256>>>(w_u2, b_u1, b_u2, out);
}